// round 2
// baseline (speedup 1.0000x reference)
#include <cuda_runtime.h>
#include <cuda_bf16.h>
#include <math.h>

// Problem constants
#define B_  8
#define S_  1024
#define D_  512
#define H_  8
#define DK_ 64

// Scratch (allocation-free: __device__ globals). 4 x 16MB.
__device__ float g_q[B_ * H_ * S_ * DK_];
__device__ float g_k[B_ * H_ * S_ * DK_];
__device__ float g_v[B_ * H_ * S_ * DK_];
__device__ float g_ctx[B_ * S_ * D_];

// ---------------- packed f32x2 helpers ----------------
__device__ __forceinline__ unsigned long long pk2(float lo, float hi) {
    unsigned long long r;
    asm("mov.b64 %0, {%1, %2};" : "=l"(r) : "f"(lo), "f"(hi));
    return r;
}
__device__ __forceinline__ void upk2(unsigned long long v, float& lo, float& hi) {
    asm("mov.b64 {%0, %1}, %2;" : "=f"(lo), "=f"(hi) : "l"(v));
}
__device__ __forceinline__ void ffma2(unsigned long long& d, unsigned long long a, unsigned long long b) {
    asm("fma.rn.f32x2 %0, %1, %2, %3;" : "=l"(d) : "l"(a), "l"(b), "l"(d));
}
__device__ __forceinline__ void fmul2(unsigned long long& d, unsigned long long a) {
    asm("mul.rn.f32x2 %0, %1, %2;" : "=l"(d) : "l"(a), "l"(d));
}

// ---------------- GEMM: C[m,n] = (sum_k A[m,k]*W[n,k] + bias[n]) * scale -------------
// A: (M,K) row-major, W: (N,K) row-major. Tile 128x128x16, 256 threads, 8x8/thread.
// headLayout=1: store to (B,H,S,64) layout; else flat (M,N).
__global__ void __launch_bounds__(256, 2)
gemm_bias(const float* __restrict__ A, const float* __restrict__ W,
          const float* __restrict__ bias, float* __restrict__ C,
          int K, int N, float scale, int headLayout)
{
    __shared__ float As[16][132];  // [k][m] transposed
    __shared__ float Ws[16][132];  // [k][n] transposed

    const int tid = threadIdx.x;
    const int ty = tid >> 4, tx = tid & 15;
    const int mBase = blockIdx.x * 128;
    const int nBase = blockIdx.y * 128;

    unsigned long long acc[8][4];
#pragma unroll
    for (int i = 0; i < 8; i++)
#pragma unroll
        for (int j = 0; j < 4; j++) acc[i][j] = 0ULL;

    for (int k0 = 0; k0 < K; k0 += 16) {
#pragma unroll
        for (int r = 0; r < 2; r++) {
            int idx = tid + 256 * r;
            int row = idx >> 2;
            int kq = (idx & 3) * 4;
            float4 av = *(const float4*)(A + (size_t)(mBase + row) * K + k0 + kq);
            As[kq + 0][row] = av.x; As[kq + 1][row] = av.y;
            As[kq + 2][row] = av.z; As[kq + 3][row] = av.w;
            float4 wv = *(const float4*)(W + (size_t)(nBase + row) * K + k0 + kq);
            Ws[kq + 0][row] = wv.x; Ws[kq + 1][row] = wv.y;
            Ws[kq + 2][row] = wv.z; Ws[kq + 3][row] = wv.w;
        }
        __syncthreads();
#pragma unroll
        for (int kk = 0; kk < 16; kk++) {
            float4 a0 = *(const float4*)&As[kk][ty * 8];
            float4 a1 = *(const float4*)&As[kk][ty * 8 + 4];
            ulonglong2 b0 = *(const ulonglong2*)&Ws[kk][tx * 8];
            ulonglong2 b1 = *(const ulonglong2*)&Ws[kk][tx * 8 + 4];
            float ar[8] = {a0.x, a0.y, a0.z, a0.w, a1.x, a1.y, a1.z, a1.w};
#pragma unroll
            for (int i = 0; i < 8; i++) {
                unsigned long long ad = pk2(ar[i], ar[i]);
                ffma2(acc[i][0], ad, b0.x);
                ffma2(acc[i][1], ad, b0.y);
                ffma2(acc[i][2], ad, b1.x);
                ffma2(acc[i][3], ad, b1.y);
            }
        }
        __syncthreads();
    }

    const int n0 = nBase + tx * 8;
    float bl[8];
#pragma unroll
    for (int j = 0; j < 8; j++) bl[j] = bias[n0 + j];

#pragma unroll
    for (int i = 0; i < 8; i++) {
        float o[8];
#pragma unroll
        for (int jp = 0; jp < 4; jp++) upk2(acc[i][jp], o[2 * jp], o[2 * jp + 1]);
#pragma unroll
        for (int j = 0; j < 8; j++) o[j] = (o[j] + bl[j]) * scale;
        int m = mBase + ty * 8 + i;
        float4 v0 = make_float4(o[0], o[1], o[2], o[3]);
        float4 v1 = make_float4(o[4], o[5], o[6], o[7]);
        if (headLayout) {
            int b = m >> 10, s = m & 1023;
            int h = n0 >> 6, d = n0 & 63;
            float* dst = C + (((size_t)(b * H_ + h) * S_ + s) * DK_ + d);
            *(float4*)dst = v0;
            *(float4*)(dst + 4) = v1;
        } else {
            float* dst = C + (size_t)m * N + n0;
            *(float4*)dst = v0;
            *(float4*)(dst + 4) = v1;
        }
    }
}

// ---------------- Flash attention with per-head-type bias ----------------
// Grid: (S/128, B*H). Block: 256 (ty=tid/16 -> 8 q rows, tx=tid%16 -> 4 k cols).
// Q tile 128 rows, K tile 64 keys, head dim 64.
__global__ void __launch_bounds__(256, 2)
attn_kernel(const float* __restrict__ Q, const float* __restrict__ Kp,
            const float* __restrict__ V, const float* __restrict__ m_it,
            const float* __restrict__ m_ist, const float* __restrict__ m_df,
            const unsigned char* __restrict__ mask, float* __restrict__ ctx)
{
    extern __shared__ float sm[];
    float* Qs = sm;                 // [64][132]  (d-major: Qs[d][qrow])
    float* Ks = Qs + 64 * 132;      // [64][68]   (d-major: Ks[d][kcol])
    float* Vs = Ks + 64 * 68;       // [64][68]   (k-major: Vs[k][d])
    float* Ps = Vs + 64 * 68;       // [64][132]  (k-major: Ps[k][qrow])

    const int tid = threadIdx.x;
    const int ty = tid >> 4, tx = tid & 15;
    const int qt = blockIdx.x, bh = blockIdx.y;
    const int b = bh >> 3, h = bh & 7;

    // Load Q tile, transposed into smem
    const float* qb = Q + ((size_t)bh * S_ + qt * 128) * DK_;
#pragma unroll
    for (int r = 0; r < 8; r++) {
        int idx = tid + 256 * r;
        int row = idx >> 4;
        int dq = (idx & 15) * 4;
        float4 v = *(const float4*)(qb + (size_t)row * DK_ + dq);
        Qs[(dq + 0) * 132 + row] = v.x; Qs[(dq + 1) * 132 + row] = v.y;
        Qs[(dq + 2) * 132 + row] = v.z; Qs[(dq + 3) * 132 + row] = v.w;
    }

    float mrow[8], lrow[8];
    unsigned long long ov[8][2];
#pragma unroll
    for (int i = 0; i < 8; i++) {
        mrow[i] = -INFINITY; lrow[i] = 0.f;
        ov[i][0] = 0ULL; ov[i][1] = 0ULL;
    }

    const float* mapP = (h < 2) ? m_it : (h < 4) ? m_ist : m_df;
    const int mode = (h < 4) ? 0 : (h < 6) ? 1 : 2;  // 0: +=-1e9*map, 1: *=(1+5*map), 2: none
    const size_t mapRowBase = ((size_t)b * S_ + qt * 128 + ty * 8) * (size_t)S_;

    for (int kt = 0; kt < 16; kt++) {
        __syncthreads();
        const float* kb = Kp + ((size_t)bh * S_ + kt * 64) * DK_;
        const float* vb = V + ((size_t)bh * S_ + kt * 64) * DK_;
#pragma unroll
        for (int r = 0; r < 4; r++) {
            int idx = tid + 256 * r;
            int row = idx >> 4;
            int dq = (idx & 15) * 4;
            float4 kv = *(const float4*)(kb + (size_t)row * DK_ + dq);
            Ks[(dq + 0) * 68 + row] = kv.x; Ks[(dq + 1) * 68 + row] = kv.y;
            Ks[(dq + 2) * 68 + row] = kv.z; Ks[(dq + 3) * 68 + row] = kv.w;
            float4 vv = *(const float4*)(vb + (size_t)row * DK_ + dq);
            *(float4*)&Vs[row * 68 + dq] = vv;
        }
        __syncthreads();

        // S = Q @ K^T  (8 rows x 4 cols per thread)
        unsigned long long sp[8][2];
#pragma unroll
        for (int i = 0; i < 8; i++) { sp[i][0] = 0ULL; sp[i][1] = 0ULL; }
#pragma unroll
        for (int d = 0; d < 64; d++) {
            float4 a0 = *(const float4*)&Qs[d * 132 + ty * 8];
            float4 a1 = *(const float4*)&Qs[d * 132 + ty * 8 + 4];
            ulonglong2 k2 = *(const ulonglong2*)&Ks[d * 68 + tx * 4];
            float ar[8] = {a0.x, a0.y, a0.z, a0.w, a1.x, a1.y, a1.z, a1.w};
#pragma unroll
            for (int i = 0; i < 8; i++) {
                unsigned long long ad = pk2(ar[i], ar[i]);
                ffma2(sp[i][0], ad, k2.x);
                ffma2(sp[i][1], ad, k2.y);
            }
        }

        float s[8][4];
#pragma unroll
        for (int i = 0; i < 8; i++) {
            upk2(sp[i][0], s[i][0], s[i][1]);
            upk2(sp[i][1], s[i][2], s[i][3]);
        }

        // Bias per head type (fp32, matches reference)
        const int kc = kt * 64 + tx * 4;
        if (mode == 0) {
#pragma unroll
            for (int i = 0; i < 8; i++) {
                float4 mp = *(const float4*)(mapP + mapRowBase + (size_t)i * S_ + kc);
                s[i][0] = fmaf(-1e9f, mp.x, s[i][0]);
                s[i][1] = fmaf(-1e9f, mp.y, s[i][1]);
                s[i][2] = fmaf(-1e9f, mp.z, s[i][2]);
                s[i][3] = fmaf(-1e9f, mp.w, s[i][3]);
            }
        } else if (mode == 1) {
#pragma unroll
            for (int i = 0; i < 8; i++) {
                float4 mp = *(const float4*)(mapP + mapRowBase + (size_t)i * S_ + kc);
                s[i][0] *= fmaf(5.f, mp.x, 1.f);
                s[i][1] *= fmaf(5.f, mp.y, 1.f);
                s[i][2] *= fmaf(5.f, mp.z, 1.f);
                s[i][3] *= fmaf(5.f, mp.w, 1.f);
            }
        }
        // Mask (key-wise)
        uchar4 mk = *(const uchar4*)(mask + b * S_ + kc);
        if (mk.x) {
#pragma unroll
            for (int i = 0; i < 8; i++) s[i][0] = -1e18f;
        }
        if (mk.y) {
#pragma unroll
            for (int i = 0; i < 8; i++) s[i][1] = -1e18f;
        }
        if (mk.z) {
#pragma unroll
            for (int i = 0; i < 8; i++) s[i][2] = -1e18f;
        }
        if (mk.w) {
#pragma unroll
            for (int i = 0; i < 8; i++) s[i][3] = -1e18f;
        }

        // Online softmax (row reductions across 16 lanes sharing ty)
#pragma unroll
        for (int i = 0; i < 8; i++) {
            float rm = fmaxf(fmaxf(s[i][0], s[i][1]), fmaxf(s[i][2], s[i][3]));
#pragma unroll
            for (int off = 8; off >= 1; off >>= 1)
                rm = fmaxf(rm, __shfl_xor_sync(0xffffffffu, rm, off));
            float nm = fmaxf(mrow[i], rm);
            float corr = __expf(mrow[i] - nm);
            mrow[i] = nm;
            float rs = 0.f;
#pragma unroll
            for (int j = 0; j < 4; j++) {
                s[i][j] = __expf(s[i][j] - nm);  // s becomes p
                rs += s[i][j];
            }
#pragma unroll
            for (int off = 8; off >= 1; off >>= 1)
                rs += __shfl_xor_sync(0xffffffffu, rs, off);
            lrow[i] = lrow[i] * corr + rs;
            unsigned long long cd = pk2(corr, corr);
            fmul2(ov[i][0], cd);
            fmul2(ov[i][1], cd);
        }

        // Store P transposed: Ps[k][qrow]
#pragma unroll
        for (int j = 0; j < 4; j++) {
            float4 u0 = make_float4(s[0][j], s[1][j], s[2][j], s[3][j]);
            float4 u1 = make_float4(s[4][j], s[5][j], s[6][j], s[7][j]);
            float* dst = &Ps[(tx * 4 + j) * 132 + ty * 8];
            *(float4*)dst = u0;
            *(float4*)(dst + 4) = u1;
        }
        __syncthreads();

        // O += P @ V
#pragma unroll
        for (int kk = 0; kk < 64; kk++) {
            float4 p0 = *(const float4*)&Ps[kk * 132 + ty * 8];
            float4 p1 = *(const float4*)&Ps[kk * 132 + ty * 8 + 4];
            ulonglong2 v2 = *(const ulonglong2*)&Vs[kk * 68 + tx * 4];
            float pr[8] = {p0.x, p0.y, p0.z, p0.w, p1.x, p1.y, p1.z, p1.w};
#pragma unroll
            for (int i = 0; i < 8; i++) {
                unsigned long long pd = pk2(pr[i], pr[i]);
                ffma2(ov[i][0], pd, v2.x);
                ffma2(ov[i][1], pd, v2.y);
            }
        }
    }

    // Epilogue: normalize and store to (B,S,H*DV) layout
#pragma unroll
    for (int i = 0; i < 8; i++) {
        float inv = 1.0f / lrow[i];
        float o0, o1, o2, o3;
        upk2(ov[i][0], o0, o1);
        upk2(ov[i][1], o2, o3);
        int srow = qt * 128 + ty * 8 + i;
        float4 w = make_float4(o0 * inv, o1 * inv, o2 * inv, o3 * inv);
        *(float4*)(ctx + ((size_t)b * S_ + srow) * D_ + h * DK_ + tx * 4) = w;
    }
}

extern "C" void kernel_launch(void* const* d_in, const int* in_sizes, int n_in,
                              void* d_out, int out_size)
{
    const float* key   = (const float*)d_in[0];
    const float* value = (const float*)d_in[1];
    const float* query = (const float*)d_in[2];
    const float* m_it  = (const float*)d_in[3];
    const float* m_ist = (const float*)d_in[4];
    const float* m_df  = (const float*)d_in[5];
    const unsigned char* mask = (const unsigned char*)d_in[6];
    const float* Wq = (const float*)d_in[7];
    const float* bq = (const float*)d_in[8];
    const float* Wk = (const float*)d_in[9];
    const float* bk = (const float*)d_in[10];
    const float* Wv = (const float*)d_in[11];
    const float* bv = (const float*)d_in[12];
    const float* Wo = (const float*)d_in[13];
    const float* bo = (const float*)d_in[14];
    float* out = (float*)d_out;

    float *gq, *gk, *gv, *gctx;
    cudaGetSymbolAddress((void**)&gq, g_q);
    cudaGetSymbolAddress((void**)&gk, g_k);
    cudaGetSymbolAddress((void**)&gv, g_v);
    cudaGetSymbolAddress((void**)&gctx, g_ctx);

    cudaFuncSetAttribute(attn_kernel, cudaFuncAttributeMaxDynamicSharedMemorySize, 102400);

    dim3 gg(64, 4), blk(256);
    // QKV projections (q pre-scaled by 1/sqrt(64))
    gemm_bias<<<gg, blk>>>(query, Wq, bq, gq, D_, D_, 0.125f, 1);
    gemm_bias<<<gg, blk>>>(key,   Wk, bk, gk, D_, D_, 1.0f,   1);
    gemm_bias<<<gg, blk>>>(value, Wv, bv, gv, D_, D_, 1.0f,   1);
    // Flash attention with head-type biases
    attn_kernel<<<dim3(8, 64), 256, 102400>>>(gq, gk, gv, m_it, m_ist, m_df, mask, gctx);
    // Output projection
    gemm_bias<<<gg, blk>>>(gctx, Wo, bo, out, D_, D_, 1.0f, 0);
}

// round 13
// speedup vs baseline: 1.2239x; 1.2239x over previous
#include <cuda_runtime.h>
#include <cuda_bf16.h>
#include <math.h>
#include <cstdint>

// Problem constants
#define B_  8
#define S_  1024
#define D_  512
#define H_  8
#define DK_ 64

// Scratch (allocation-free: __device__ globals).
__device__ float g_q[B_ * H_ * S_ * DK_];
__device__ float g_k[B_ * H_ * S_ * DK_];
__device__ float g_v[B_ * H_ * S_ * DK_];
__device__ float g_ctx[B_ * S_ * D_];

// ---------------- packed f32x2 helpers (attention kernel) ----------------
__device__ __forceinline__ unsigned long long pk2(float lo, float hi) {
    unsigned long long r;
    asm("mov.b64 %0, {%1, %2};" : "=l"(r) : "f"(lo), "f"(hi));
    return r;
}
__device__ __forceinline__ void upk2(unsigned long long v, float& lo, float& hi) {
    asm("mov.b64 {%0, %1}, %2;" : "=f"(lo), "=f"(hi) : "l"(v));
}
__device__ __forceinline__ void ffma2(unsigned long long& d, unsigned long long a, unsigned long long b) {
    asm("fma.rn.f32x2 %0, %1, %2, %3;" : "=l"(d) : "l"(a), "l"(b), "l"(d));
}
__device__ __forceinline__ void fmul2(unsigned long long& d, unsigned long long a) {
    asm("mul.rn.f32x2 %0, %1, %2;" : "=l"(d) : "l"(a), "l"(d));
}

// ---------------- mma.sync helpers (compute_103-safe: HMMA path) ----------------
__device__ __forceinline__ uint32_t smem_u32(const void* p) {
    uint32_t a;
    asm("{ .reg .u64 t; cvta.to.shared.u64 t, %1; cvt.u32.u64 %0, t; }" : "=r"(a) : "l"(p));
    return a;
}
__device__ __forceinline__ void ldmx4(uint32_t* r, uint32_t addr) {
    asm volatile("ldmatrix.sync.aligned.m8n8.x4.shared.b16 {%0,%1,%2,%3}, [%4];"
                 : "=r"(r[0]), "=r"(r[1]), "=r"(r[2]), "=r"(r[3]) : "r"(addr));
}
__device__ __forceinline__ void mma_bf16(float* d, const uint32_t* a, uint32_t b0, uint32_t b1) {
    asm volatile(
        "mma.sync.aligned.m16n8k16.row.col.f32.bf16.bf16.f32 "
        "{%0,%1,%2,%3}, {%4,%5,%6,%7}, {%8,%9}, {%0,%1,%2,%3};"
        : "+f"(d[0]), "+f"(d[1]), "+f"(d[2]), "+f"(d[3])
        : "r"(a[0]), "r"(a[1]), "r"(a[2]), "r"(a[3]), "r"(b0), "r"(b1));
}

// ---------------- mma.sync GEMM: C[m,n] = (sum_k A[m,k]*W[n,k] + bias[n]) * scale ----
// M=8192, N=512, K=512. CTA tile 128x128, 8 warps of 32x64. K-chunks of 32.
// bf16 hi/lo split, 3 products per mma triple -> ~1e-5 accuracy.
struct GemmArgs {
    const float* A[3];
    const float* W[3];
    const float* bias[3];
    float* C[3];
    float scale[3];
    int headLayout;
    int nz;
};

#define LDB  80                     // smem row stride in bytes (40 bf16)
#define TILE_BYTES (128 * LDB)      // 10240
#define OFF_AHI 0
#define OFF_ALO (TILE_BYTES)
#define OFF_WHI (2 * TILE_BYTES)
#define OFF_WLO (3 * TILE_BYTES)
#define SM_GEMM_SZ (4 * TILE_BYTES) // 40960

__device__ __forceinline__ void split4(float4 v, uint2& hv, uint2& lv) {
    __nv_bfloat16 h0 = __float2bfloat16(v.x);
    __nv_bfloat16 h1 = __float2bfloat16(v.y);
    __nv_bfloat16 h2 = __float2bfloat16(v.z);
    __nv_bfloat16 h3 = __float2bfloat16(v.w);
    __nv_bfloat16 l0 = __float2bfloat16(v.x - __bfloat162float(h0));
    __nv_bfloat16 l1 = __float2bfloat16(v.y - __bfloat162float(h1));
    __nv_bfloat16 l2 = __float2bfloat16(v.z - __bfloat162float(h2));
    __nv_bfloat16 l3 = __float2bfloat16(v.w - __bfloat162float(h3));
    __nv_bfloat162 hA; hA.x = h0; hA.y = h1;
    __nv_bfloat162 hB; hB.x = h2; hB.y = h3;
    __nv_bfloat162 lA; lA.x = l0; lA.y = l1;
    __nv_bfloat162 lB; lB.x = l2; lB.y = l3;
    hv = make_uint2(*(uint32_t*)&hA, *(uint32_t*)&hB);
    lv = make_uint2(*(uint32_t*)&lA, *(uint32_t*)&lB);
}

__global__ void __launch_bounds__(256)
gemm_mma(GemmArgs ga)
{
    extern __shared__ __align__(16) char smg[];
    const int tid = threadIdx.x;
    const int wid = tid >> 5, lane = tid & 31;
    const int z = blockIdx.z;
    const int mBase = blockIdx.x * 128;
    const int nBase = blockIdx.y * 128;

    const float* A = ga.A[z];
    const float* W = ga.W[z];
    const float* bias = ga.bias[z];
    float* C = ga.C[z];
    const float scale = ga.scale[z];

    const int wm = (wid >> 1) * 32;   // warp row offset within tile (0,32,64,96)
    const int wn = (wid & 1) * 64;    // warp col offset (0,64)

    const uint32_t sb = smem_u32(smg);
    const uint32_t sAhi = sb + OFF_AHI, sAlo = sb + OFF_ALO;
    const uint32_t sWhi = sb + OFF_WHI, sWlo = sb + OFF_WLO;

    float acc[2][8][4];
#pragma unroll
    for (int i = 0; i < 2; i++)
#pragma unroll
        for (int j = 0; j < 8; j++)
#pragma unroll
            for (int c = 0; c < 4; c++) acc[i][j][c] = 0.f;

    for (int kc = 0; kc < 512; kc += 32) {
        __syncthreads();
        // Load + hi/lo-split A tile (128x32) and W tile (128x32)
#pragma unroll
        for (int r = 0; r < 4; r++) {
            int idx = tid + 256 * r;
            int row = idx >> 3;
            int c4 = (idx & 7) * 4;
            uint32_t off = (uint32_t)(row * LDB + c4 * 2);
            uint2 hv, lv;
            split4(*(const float4*)(A + (size_t)(mBase + row) * 512 + kc + c4), hv, lv);
            *(uint2*)(smg + OFF_AHI + off) = hv;
            *(uint2*)(smg + OFF_ALO + off) = lv;
            split4(*(const float4*)(W + (size_t)(nBase + row) * 512 + kc + c4), hv, lv);
            *(uint2*)(smg + OFF_WHI + off) = hv;
            *(uint2*)(smg + OFF_WLO + off) = lv;
        }
        __syncthreads();

#pragma unroll
        for (int ks = 0; ks < 2; ks++) {
            // A fragments: 2 row-blocks of 16, hi and lo
            uint32_t ahi[2][4], alo[2][4];
#pragma unroll
            for (int rb = 0; rb < 2; rb++) {
                int arow = wm + rb * 16 + (lane & 15);
                int acol = ks * 16 + (lane >> 4) * 8;
                uint32_t aoff = (uint32_t)(arow * LDB + acol * 2);
                ldmx4(ahi[rb], sAhi + aoff);
                ldmx4(alo[rb], sAlo + aoff);
            }
            // B fragment pairs: 4 pairs of n-blocks (8 n-blocks total)
#pragma unroll
            for (int nbp = 0; nbp < 4; nbp++) {
                int g = lane >> 3, rr = lane & 7;
                int brow = wn + nbp * 16 + (g >> 1) * 8 + rr;
                int bcol = ks * 16 + (g & 1) * 8;
                uint32_t boff = (uint32_t)(brow * LDB + bcol * 2);
                uint32_t bh[4], bl[4];
                ldmx4(bh, sWhi + boff);
                ldmx4(bl, sWlo + boff);
#pragma unroll
                for (int rb = 0; rb < 2; rb++) {
                    float* a0 = acc[rb][nbp * 2 + 0];
                    float* a1 = acc[rb][nbp * 2 + 1];
                    mma_bf16(a0, ahi[rb], bh[0], bh[1]);
                    mma_bf16(a0, ahi[rb], bl[0], bl[1]);
                    mma_bf16(a0, alo[rb], bh[0], bh[1]);
                    mma_bf16(a1, ahi[rb], bh[2], bh[3]);
                    mma_bf16(a1, ahi[rb], bl[2], bl[3]);
                    mma_bf16(a1, alo[rb], bh[2], bh[3]);
                }
            }
        }
    }

    // Epilogue: d0,d1 -> (row qr, cols qc..qc+1); d2,d3 -> (row qr+8)
    const int qr = lane >> 2, qc = (lane & 3) * 2;
#pragma unroll
    for (int rb = 0; rb < 2; rb++) {
#pragma unroll
        for (int nb = 0; nb < 8; nb++) {
            int n0 = nBase + wn + nb * 8 + qc;
            float b0 = bias[n0], b1 = bias[n0 + 1];
#pragma unroll
            for (int half = 0; half < 2; half++) {
                int m = mBase + wm + rb * 16 + qr + half * 8;
                float v0 = (acc[rb][nb][half * 2 + 0] + b0) * scale;
                float v1 = (acc[rb][nb][half * 2 + 1] + b1) * scale;
                float* dst;
                if (ga.headLayout) {
                    int b = m >> 10, s = m & 1023;
                    int h = n0 >> 6, d0 = n0 & 63;
                    dst = C + (((size_t)(b * H_ + h) * S_ + s) * DK_ + d0);
                } else {
                    dst = C + (size_t)m * 512 + n0;
                }
                *(float2*)dst = make_float2(v0, v1);
            }
        }
    }
}

// ---------------- Flash attention with per-head-type bias (unchanged, verified) --------
__global__ void __launch_bounds__(256, 2)
attn_kernel(const float* __restrict__ Q, const float* __restrict__ Kp,
            const float* __restrict__ V, const float* __restrict__ m_it,
            const float* __restrict__ m_ist, const float* __restrict__ m_df,
            const unsigned char* __restrict__ mask, float* __restrict__ ctx)
{
    extern __shared__ float sm[];
    float* Qs = sm;                 // [64][132]
    float* Ks = Qs + 64 * 132;      // [64][68]
    float* Vs = Ks + 64 * 68;       // [64][68]
    float* Ps = Vs + 64 * 68;       // [64][132]

    const int tid = threadIdx.x;
    const int ty = tid >> 4, tx = tid & 15;
    const int qt = blockIdx.x, bh = blockIdx.y;
    const int b = bh >> 3, h = bh & 7;

    const float* qb = Q + ((size_t)bh * S_ + qt * 128) * DK_;
#pragma unroll
    for (int r = 0; r < 8; r++) {
        int idx = tid + 256 * r;
        int row = idx >> 4;
        int dq = (idx & 15) * 4;
        float4 v = *(const float4*)(qb + (size_t)row * DK_ + dq);
        Qs[(dq + 0) * 132 + row] = v.x; Qs[(dq + 1) * 132 + row] = v.y;
        Qs[(dq + 2) * 132 + row] = v.z; Qs[(dq + 3) * 132 + row] = v.w;
    }

    float mrow[8], lrow[8];
    unsigned long long ov[8][2];
#pragma unroll
    for (int i = 0; i < 8; i++) {
        mrow[i] = -INFINITY; lrow[i] = 0.f;
        ov[i][0] = 0ULL; ov[i][1] = 0ULL;
    }

    const float* mapP = (h < 2) ? m_it : (h < 4) ? m_ist : m_df;
    const int mode = (h < 4) ? 0 : (h < 6) ? 1 : 2;
    const size_t mapRowBase = ((size_t)b * S_ + qt * 128 + ty * 8) * (size_t)S_;

    for (int kt = 0; kt < 16; kt++) {
        __syncthreads();
        const float* kb = Kp + ((size_t)bh * S_ + kt * 64) * DK_;
        const float* vb = V + ((size_t)bh * S_ + kt * 64) * DK_;
#pragma unroll
        for (int r = 0; r < 4; r++) {
            int idx = tid + 256 * r;
            int row = idx >> 4;
            int dq = (idx & 15) * 4;
            float4 kv = *(const float4*)(kb + (size_t)row * DK_ + dq);
            Ks[(dq + 0) * 68 + row] = kv.x; Ks[(dq + 1) * 68 + row] = kv.y;
            Ks[(dq + 2) * 68 + row] = kv.z; Ks[(dq + 3) * 68 + row] = kv.w;
            float4 vv = *(const float4*)(vb + (size_t)row * DK_ + dq);
            *(float4*)&Vs[row * 68 + dq] = vv;
        }
        __syncthreads();

        unsigned long long sp[8][2];
#pragma unroll
        for (int i = 0; i < 8; i++) { sp[i][0] = 0ULL; sp[i][1] = 0ULL; }
#pragma unroll
        for (int d = 0; d < 64; d++) {
            float4 a0 = *(const float4*)&Qs[d * 132 + ty * 8];
            float4 a1 = *(const float4*)&Qs[d * 132 + ty * 8 + 4];
            ulonglong2 k2 = *(const ulonglong2*)&Ks[d * 68 + tx * 4];
            float ar[8] = {a0.x, a0.y, a0.z, a0.w, a1.x, a1.y, a1.z, a1.w};
#pragma unroll
            for (int i = 0; i < 8; i++) {
                unsigned long long ad = pk2(ar[i], ar[i]);
                ffma2(sp[i][0], ad, k2.x);
                ffma2(sp[i][1], ad, k2.y);
            }
        }

        float s[8][4];
#pragma unroll
        for (int i = 0; i < 8; i++) {
            upk2(sp[i][0], s[i][0], s[i][1]);
            upk2(sp[i][1], s[i][2], s[i][3]);
        }

        const int kc = kt * 64 + tx * 4;
        if (mode == 0) {
#pragma unroll
            for (int i = 0; i < 8; i++) {
                float4 mp = *(const float4*)(mapP + mapRowBase + (size_t)i * S_ + kc);
                s[i][0] = fmaf(-1e9f, mp.x, s[i][0]);
                s[i][1] = fmaf(-1e9f, mp.y, s[i][1]);
                s[i][2] = fmaf(-1e9f, mp.z, s[i][2]);
                s[i][3] = fmaf(-1e9f, mp.w, s[i][3]);
            }
        } else if (mode == 1) {
#pragma unroll
            for (int i = 0; i < 8; i++) {
                float4 mp = *(const float4*)(mapP + mapRowBase + (size_t)i * S_ + kc);
                s[i][0] *= fmaf(5.f, mp.x, 1.f);
                s[i][1] *= fmaf(5.f, mp.y, 1.f);
                s[i][2] *= fmaf(5.f, mp.z, 1.f);
                s[i][3] *= fmaf(5.f, mp.w, 1.f);
            }
        }
        uchar4 mk = *(const uchar4*)(mask + b * S_ + kc);
        if (mk.x) {
#pragma unroll
            for (int i = 0; i < 8; i++) s[i][0] = -1e18f;
        }
        if (mk.y) {
#pragma unroll
            for (int i = 0; i < 8; i++) s[i][1] = -1e18f;
        }
        if (mk.z) {
#pragma unroll
            for (int i = 0; i < 8; i++) s[i][2] = -1e18f;
        }
        if (mk.w) {
#pragma unroll
            for (int i = 0; i < 8; i++) s[i][3] = -1e18f;
        }

#pragma unroll
        for (int i = 0; i < 8; i++) {
            float rm = fmaxf(fmaxf(s[i][0], s[i][1]), fmaxf(s[i][2], s[i][3]));
#pragma unroll
            for (int off = 8; off >= 1; off >>= 1)
                rm = fmaxf(rm, __shfl_xor_sync(0xffffffffu, rm, off));
            float nm = fmaxf(mrow[i], rm);
            float corr = __expf(mrow[i] - nm);
            mrow[i] = nm;
            float rs = 0.f;
#pragma unroll
            for (int j = 0; j < 4; j++) {
                s[i][j] = __expf(s[i][j] - nm);
                rs += s[i][j];
            }
#pragma unroll
            for (int off = 8; off >= 1; off >>= 1)
                rs += __shfl_xor_sync(0xffffffffu, rs, off);
            lrow[i] = lrow[i] * corr + rs;
            unsigned long long cd = pk2(corr, corr);
            fmul2(ov[i][0], cd);
            fmul2(ov[i][1], cd);
        }

#pragma unroll
        for (int j = 0; j < 4; j++) {
            float4 u0 = make_float4(s[0][j], s[1][j], s[2][j], s[3][j]);
            float4 u1 = make_float4(s[4][j], s[5][j], s[6][j], s[7][j]);
            float* dst = &Ps[(tx * 4 + j) * 132 + ty * 8];
            *(float4*)dst = u0;
            *(float4*)(dst + 4) = u1;
        }
        __syncthreads();

#pragma unroll
        for (int kk = 0; kk < 64; kk++) {
            float4 p0 = *(const float4*)&Ps[kk * 132 + ty * 8];
            float4 p1 = *(const float4*)&Ps[kk * 132 + ty * 8 + 4];
            ulonglong2 v2 = *(const ulonglong2*)&Vs[kk * 68 + tx * 4];
            float pr[8] = {p0.x, p0.y, p0.z, p0.w, p1.x, p1.y, p1.z, p1.w};
#pragma unroll
            for (int i = 0; i < 8; i++) {
                unsigned long long pd = pk2(pr[i], pr[i]);
                ffma2(ov[i][0], pd, v2.x);
                ffma2(ov[i][1], pd, v2.y);
            }
        }
    }

#pragma unroll
    for (int i = 0; i < 8; i++) {
        float inv = 1.0f / lrow[i];
        float o0, o1, o2, o3;
        upk2(ov[i][0], o0, o1);
        upk2(ov[i][1], o2, o3);
        int srow = qt * 128 + ty * 8 + i;
        float4 w = make_float4(o0 * inv, o1 * inv, o2 * inv, o3 * inv);
        *(float4*)(ctx + ((size_t)b * S_ + srow) * D_ + h * DK_ + tx * 4) = w;
    }
}

extern "C" void kernel_launch(void* const* d_in, const int* in_sizes, int n_in,
                              void* d_out, int out_size)
{
    const float* key   = (const float*)d_in[0];
    const float* value = (const float*)d_in[1];
    const float* query = (const float*)d_in[2];
    const float* m_it  = (const float*)d_in[3];
    const float* m_ist = (const float*)d_in[4];
    const float* m_df  = (const float*)d_in[5];
    const unsigned char* mask = (const unsigned char*)d_in[6];
    const float* Wq = (const float*)d_in[7];
    const float* bq = (const float*)d_in[8];
    const float* Wk = (const float*)d_in[9];
    const float* bk = (const float*)d_in[10];
    const float* Wv = (const float*)d_in[11];
    const float* bv = (const float*)d_in[12];
    const float* Wo = (const float*)d_in[13];
    const float* bo = (const float*)d_in[14];
    float* out = (float*)d_out;

    float *gq, *gk, *gv, *gctx;
    cudaGetSymbolAddress((void**)&gq, g_q);
    cudaGetSymbolAddress((void**)&gk, g_k);
    cudaGetSymbolAddress((void**)&gv, g_v);
    cudaGetSymbolAddress((void**)&gctx, g_ctx);

    cudaFuncSetAttribute(attn_kernel, cudaFuncAttributeMaxDynamicSharedMemorySize, 102400);

    // Fused QKV projections (z selects input/weight/output; q pre-scaled by 1/8)
    GemmArgs qkv;
    qkv.A[0] = query; qkv.A[1] = key;  qkv.A[2] = value;
    qkv.W[0] = Wq;    qkv.W[1] = Wk;   qkv.W[2] = Wv;
    qkv.bias[0] = bq; qkv.bias[1] = bk; qkv.bias[2] = bv;
    qkv.C[0] = gq;    qkv.C[1] = gk;   qkv.C[2] = gv;
    qkv.scale[0] = 0.125f; qkv.scale[1] = 1.0f; qkv.scale[2] = 1.0f;
    qkv.headLayout = 1; qkv.nz = 3;
    gemm_mma<<<dim3(64, 4, 3), 256, SM_GEMM_SZ>>>(qkv);

    // Flash attention with head-type biases
    attn_kernel<<<dim3(8, 64), 256, 102400>>>(gq, gk, gv, m_it, m_ist, m_df, mask, gctx);

    // Output projection
    GemmArgs op;
    op.A[0] = gctx; op.A[1] = gctx; op.A[2] = gctx;
    op.W[0] = Wo;   op.W[1] = Wo;   op.W[2] = Wo;
    op.bias[0] = bo; op.bias[1] = bo; op.bias[2] = bo;
    op.C[0] = out;  op.C[1] = out;  op.C[2] = out;
    op.scale[0] = 1.0f; op.scale[1] = 1.0f; op.scale[2] = 1.0f;
    op.headLayout = 0; op.nz = 1;
    gemm_mma<<<dim3(64, 4, 1), 256, SM_GEMM_SZ>>>(op);
}